// round 14
// baseline (speedup 1.0000x reference)
#include <cuda_runtime.h>

// Half-lattice hop operator, cp.async (LDGSTS) pipelined K stream:
//   out = DIAG*psi - 0.5 * sum_mu ( K_fwd[mu] @ psi(fwd nbr) + K_bwd[mu] @ psi(bwd nbr) )
// T=Z=Y=16, X/2=8, D=12 complex. mu<3: periodic roll; mu=3: parity-gated X hop.
//
// 16 sites/block, 192 threads (thread = site x output-row). K for each of the
// 8 stages (mu x fwd/bwd) is DMA'd GMEM->SMEM with cp.async.cg, double-buffered.
// Fix vs R12/13: final stage must wait_group 0 (its group is the newest commit).

#define DD 12
#define NV (16*16*16*8)            // 32768 sites
#define DIAGC 4.5f
#define KSTRIDE (NV*DD*DD)         // floats per (mu) slab
#define SLABF (16*DD*DD)           // 2304 floats = one block's K slice, one comp

__device__ __forceinline__ unsigned smem_u32(const void* p) {
    unsigned a;
    asm("{ .reg .u64 t; cvta.to.shared.u64 t, %1; cvt.u32.u64 %0, t; }"
        : "=r"(a) : "l"(p));
    return a;
}

__global__ __launch_bounds__(192)
void hop_kernel(const float* __restrict__ psr, const float* __restrict__ psi_,
                const float* __restrict__ Kfr, const float* __restrict__ Kfi,
                const float* __restrict__ Kbr, const float* __restrict__ Kbi,
                float* __restrict__ out)
{
    __shared__ float sK[2][2][SLABF];   // [buf][re/im][2304] = 36864 B

    const int i  = threadIdx.x;          // 0..11 output row
    const int ty = threadIdx.y;          // 0..15 site in block
    const int tid = ty * 12 + i;         // 0..191
    const int site0 = blockIdx.x * 16;
    const int site  = site0 + ty;

    // site bits: x [0:3), y [3:7), z [7:11), t [11:15)
    const int x = site & 7;
    const int y = (site >> 3) & 15;
    const int z = (site >> 7) & 15;
    const int t = (site >> 11) & 15;
    const int r = (t + z + y) & 1;

    // neighbor quad offsets into psi (site*12 floats = site*3 float4)
    const unsigned nn[8] = {
        ((site & ~(15<<11)) | (((t+1)&15)<<11)) * 3u,   // T fwd
        ((site & ~(15<<11)) | (((t+15)&15)<<11)) * 3u,  // T bwd
        ((site & ~(15<<7))  | (((z+1)&15)<<7)) * 3u,    // Z fwd
        ((site & ~(15<<7))  | (((z+15)&15)<<7)) * 3u,   // Z bwd
        ((site & ~(15<<3))  | (((y+1)&15)<<3)) * 3u,    // Y fwd
        ((site & ~(15<<3))  | (((y+15)&15)<<3)) * 3u,   // Y bwd
        (unsigned)(r ? ((site & ~7) | ((x+1)&7)) : site) * 3u,   // X fwd iff r==1
        (unsigned)(r ? site : ((site & ~7) | ((x+7)&7))) * 3u    // X bwd iff r==0
    };

    const float4* pr4 = reinterpret_cast<const float4*>(psr);
    const float4* pi4 = reinterpret_cast<const float4*>(psi_);

    const unsigned sb = smem_u32(&sK[0][0][0]);
    const unsigned my48 = (unsigned)tid * 48u;   // this thread's 48-B copy chunk

    // fill stage s (s>>1 = mu, s&1 = bwd) into buffer buf; one commit group
#define FILL(buf, s) { \
    const float* srR = ((s) & 1 ? Kbr : Kfr) + ((s) >> 1) * KSTRIDE + site0 * 144 + tid * 12; \
    const float* srI = ((s) & 1 ? Kbi : Kfi) + ((s) >> 1) * KSTRIDE + site0 * 144 + tid * 12; \
    const unsigned dR = sb + (unsigned)((buf) * 2 + 0) * (SLABF * 4) + my48; \
    const unsigned dI = sb + (unsigned)((buf) * 2 + 1) * (SLABF * 4) + my48; \
    asm volatile("cp.async.cg.shared.global [%0], [%1], 16;" :: "r"(dR),      "l"(srR)     : "memory"); \
    asm volatile("cp.async.cg.shared.global [%0], [%1], 16;" :: "r"(dR + 16), "l"(srR + 4) : "memory"); \
    asm volatile("cp.async.cg.shared.global [%0], [%1], 16;" :: "r"(dR + 32), "l"(srR + 8) : "memory"); \
    asm volatile("cp.async.cg.shared.global [%0], [%1], 16;" :: "r"(dI),      "l"(srI)     : "memory"); \
    asm volatile("cp.async.cg.shared.global [%0], [%1], 16;" :: "r"(dI + 16), "l"(srI + 4) : "memory"); \
    asm volatile("cp.async.cg.shared.global [%0], [%1], 16;" :: "r"(dI + 32), "l"(srI + 8) : "memory"); \
    asm volatile("cp.async.commit_group;" ::: "memory"); }

    FILL(0, 0);
    FILL(1, 1);

    float hr0 = 0.f, hi0 = 0.f, hr1 = 0.f, hi1 = 0.f;
    const unsigned rowf = (unsigned)ty * 144u + (unsigned)i * 12u;  // float offset in slab

#pragma unroll
    for (int s = 0; s < 8; ++s) {
        // stage s's group must be complete. For s<7 one newer group may still be
        // in flight (wait_group 1); at s==7 stage 7 IS the newest group -> wait 0.
        if (s == 7) { asm volatile("cp.async.wait_group 0;" ::: "memory"); }
        else        { asm volatile("cp.async.wait_group 1;" ::: "memory"); }
        __syncthreads();
        {
            const float4* kr = reinterpret_cast<const float4*>(&sK[s & 1][0][rowf]);
            const float4* ki = reinterpret_cast<const float4*>(&sK[s & 1][1][rowf]);
#pragma unroll
            for (int c = 0; c < 3; ++c) {
                const float4 krv = kr[c];
                const float4 kiv = ki[c];
                const float4 vr = __ldg(pr4 + nn[s] + c);
                const float4 vi = __ldg(pi4 + nn[s] + c);
                hr0 = fmaf(krv.x, vr.x, hr0); hr0 = fmaf(-kiv.x, vi.x, hr0);
                hi0 = fmaf(krv.x, vi.x, hi0); hi0 = fmaf( kiv.x, vr.x, hi0);
                hr1 = fmaf(krv.y, vr.y, hr1); hr1 = fmaf(-kiv.y, vi.y, hr1);
                hi1 = fmaf(krv.y, vi.y, hi1); hi1 = fmaf( kiv.y, vr.y, hi1);
                hr0 = fmaf(krv.z, vr.z, hr0); hr0 = fmaf(-kiv.z, vi.z, hr0);
                hi0 = fmaf(krv.z, vi.z, hi0); hi0 = fmaf( kiv.z, vr.z, hi0);
                hr1 = fmaf(krv.w, vr.w, hr1); hr1 = fmaf(-kiv.w, vi.w, hr1);
                hi1 = fmaf(krv.w, vi.w, hi1); hi1 = fmaf( kiv.w, vr.w, hi1);
            }
        }
        __syncthreads();                   // everyone done reading buf[s&1]
        if (s < 6) {
            switch (s) {                   // refill freed buffer with stage s+2
            case 0: FILL(0, 2); break;
            case 1: FILL(1, 3); break;
            case 2: FILL(0, 4); break;
            case 3: FILL(1, 5); break;
            case 4: FILL(0, 6); break;
            default: FILL(1, 7); break;
            }
        }
    }
#undef FILL

    const unsigned so = (unsigned)site * DD + (unsigned)i;
    const float pre = __ldg(psr + so);
    const float pim = __ldg(psi_ + so);
    out[so]           = DIAGC * pre - 0.5f * (hr0 + hr1);
    out[NV * DD + so] = DIAGC * pim - 0.5f * (hi0 + hi1);
}

extern "C" void kernel_launch(void* const* d_in, const int* in_sizes, int n_in,
                              void* d_out, int out_size)
{
    const float* psr = (const float*)d_in[0];
    const float* psi = (const float*)d_in[1];
    const float* Kfr = (const float*)d_in[2];
    const float* Kfi = (const float*)d_in[3];
    const float* Kbr = (const float*)d_in[4];
    const float* Kbi = (const float*)d_in[5];
    float* out = (float*)d_out;

    dim3 block(12, 16);      // 12 rows x 16 sites = 192 threads
    dim3 grid(NV / 16);      // 2048 blocks
    hop_kernel<<<grid, block>>>(psr, psi, Kfr, Kfi, Kbr, Kbi, out);
}

// round 17
// speedup vs baseline: 1.1010x; 1.1010x over previous
#include <cuda_runtime.h>

// Half-lattice hop, deep cp.async pipeline with DENSE lane mapping:
//   out = DIAG*psi - 0.5 * sum_mu ( K_fwd[mu] @ psi(fwd nbr) + K_bwd[mu] @ psi(bwd nbr) )
// 16 sites/block, 192 threads. K stream: 8 stages (mu x fwd/bwd), 5 smem
// buffers, 4 stages in flight, one barrier per stage. Fill lanes are
// contiguous (4 lines per LDGSTS warp-op vs 12 on the register-LDG path).

#define DD 12
#define NV (16*16*16*8)            // 32768 sites
#define DIAGC 4.5f
#define KSTRIDE (NV*DD*DD)         // floats per (mu) slab
#define SLABF 2304                 // floats: 16 sites x 144, one comp
#define STAGEB (2*SLABF*4)         // 18432 B per stage (re+im)
#define NBUF 5

__device__ __forceinline__ unsigned smem_u32(const void* p) {
    unsigned a;
    asm("{ .reg .u64 t; cvta.to.shared.u64 t, %1; cvt.u32.u64 %0, t; }"
        : "=r"(a) : "l"(p));
    return a;
}

__global__ __launch_bounds__(192)
void hop_kernel(const float* __restrict__ psr, const float* __restrict__ psi_,
                const float* __restrict__ Kfr, const float* __restrict__ Kfi,
                const float* __restrict__ Kbr, const float* __restrict__ Kbi,
                float* __restrict__ out)
{
    extern __shared__ float sK[];        // NBUF * 4608 floats = 92160 B

    const int i  = threadIdx.x;          // 0..11 output row
    const int ty = threadIdx.y;          // 0..15 site in block
    const int tid = ty * 12 + i;         // 0..191
    const int site0 = blockIdx.x * 16;
    const int site  = site0 + ty;

    const int x = site & 7;
    const int y = (site >> 3) & 15;
    const int z = (site >> 7) & 15;
    const int t = (site >> 11) & 15;
    const int r = (t + z + y) & 1;

    const unsigned nn[8] = {
        ((site & ~(15<<11)) | (((t+1)&15)<<11)) * 3u,   // T fwd
        ((site & ~(15<<11)) | (((t+15)&15)<<11)) * 3u,  // T bwd
        ((site & ~(15<<7))  | (((z+1)&15)<<7)) * 3u,    // Z fwd
        ((site & ~(15<<7))  | (((z+15)&15)<<7)) * 3u,   // Z bwd
        ((site & ~(15<<3))  | (((y+1)&15)<<3)) * 3u,    // Y fwd
        ((site & ~(15<<3))  | (((y+15)&15)<<3)) * 3u,   // Y bwd
        (unsigned)(r ? ((site & ~7) | ((x+1)&7)) : site) * 3u,   // X fwd iff r==1
        (unsigned)(r ? site : ((site & ~7) | ((x+7)&7))) * 3u    // X bwd iff r==0
    };

    const float4* pr4 = reinterpret_cast<const float4*>(psr);
    const float4* pi4 = reinterpret_cast<const float4*>(psi_);
    const unsigned sb = smem_u32(sK);
    const unsigned gbase = (unsigned)site0 * 144u;   // float offset of block's K slice

    // Dense fill: thread copies 16-B chunks tid, tid+192, tid+384 of re and im.
    // Warp lanes contiguous -> each LDGSTS warp-op covers 512 B (4 lines).
#define FILL(s) { \
    const int buf_ = (s) % NBUF; \
    const float* gR = (((s) & 1) ? Kbr : Kfr) + ((s) >> 1) * KSTRIDE + gbase; \
    const float* gI = (((s) & 1) ? Kbi : Kfi) + ((s) >> 1) * KSTRIDE + gbase; \
    const unsigned dR = sb + (unsigned)buf_ * STAGEB + (unsigned)tid * 16u; \
    const unsigned dI = dR + (unsigned)SLABF * 4u; \
    asm volatile("cp.async.cg.shared.global [%0], [%1], 16;" :: "r"(dR),            "l"(gR + tid * 4)       : "memory"); \
    asm volatile("cp.async.cg.shared.global [%0], [%1], 16;" :: "r"(dR + 192*16),   "l"(gR + tid * 4 + 768) : "memory"); \
    asm volatile("cp.async.cg.shared.global [%0], [%1], 16;" :: "r"(dR + 384*16),   "l"(gR + tid * 4 + 1536): "memory"); \
    asm volatile("cp.async.cg.shared.global [%0], [%1], 16;" :: "r"(dI),            "l"(gI + tid * 4)       : "memory"); \
    asm volatile("cp.async.cg.shared.global [%0], [%1], 16;" :: "r"(dI + 192*16),   "l"(gI + tid * 4 + 768) : "memory"); \
    asm volatile("cp.async.cg.shared.global [%0], [%1], 16;" :: "r"(dI + 384*16),   "l"(gI + tid * 4 + 1536): "memory"); \
    asm volatile("cp.async.commit_group;" ::: "memory"); }

    FILL(0); FILL(1); FILL(2); FILL(3);   // 4 stages in flight

    float hr0 = 0.f, hi0 = 0.f, hr1 = 0.f, hi1 = 0.f;
    const unsigned rowf = (unsigned)ty * 144u + (unsigned)i * 12u;

#pragma unroll
    for (int s = 0; s < 8; ++s) {
        // stage s's group must be done; allow the newer pending ones.
        if      (s == 7) asm volatile("cp.async.wait_group 0;" ::: "memory");
        else if (s == 6) asm volatile("cp.async.wait_group 1;" ::: "memory");
        else if (s == 5) asm volatile("cp.async.wait_group 2;" ::: "memory");
        else             asm volatile("cp.async.wait_group 3;" ::: "memory");
        __syncthreads();   // all copies visible; all threads past stage s-1 compute
        if (s < 4) FILL(s + 4);   // into buf (s+4)%5 = (s-1)%5, drained last iter
        {
            const float* base = sK + (s % NBUF) * (2 * SLABF);
            const float4* kr = reinterpret_cast<const float4*>(base + rowf);
            const float4* ki = reinterpret_cast<const float4*>(base + SLABF + rowf);
#pragma unroll
            for (int c = 0; c < 3; ++c) {
                const float4 krv = kr[c];
                const float4 kiv = ki[c];
                const float4 vr = __ldg(pr4 + nn[s] + c);
                const float4 vi = __ldg(pi4 + nn[s] + c);
                hr0 = fmaf(krv.x, vr.x, hr0); hr0 = fmaf(-kiv.x, vi.x, hr0);
                hi0 = fmaf(krv.x, vi.x, hi0); hi0 = fmaf( kiv.x, vr.x, hi0);
                hr1 = fmaf(krv.y, vr.y, hr1); hr1 = fmaf(-kiv.y, vi.y, hr1);
                hi1 = fmaf(krv.y, vi.y, hi1); hi1 = fmaf( kiv.y, vr.y, hi1);
                hr0 = fmaf(krv.z, vr.z, hr0); hr0 = fmaf(-kiv.z, vi.z, hr0);
                hi0 = fmaf(krv.z, vi.z, hi0); hi0 = fmaf( kiv.z, vr.z, hi0);
                hr1 = fmaf(krv.w, vr.w, hr1); hr1 = fmaf(-kiv.w, vi.w, hr1);
                hi1 = fmaf(krv.w, vi.w, hi1); hi1 = fmaf( kiv.w, vr.w, hi1);
            }
        }
    }
#undef FILL

    const unsigned so = (unsigned)site * DD + (unsigned)i;
    const float pre = __ldg(psr + so);
    const float pim = __ldg(psi_ + so);
    out[so]           = DIAGC * pre - 0.5f * (hr0 + hr1);
    out[NV * DD + so] = DIAGC * pim - 0.5f * (hi0 + hi1);
}

extern "C" void kernel_launch(void* const* d_in, const int* in_sizes, int n_in,
                              void* d_out, int out_size)
{
    const float* psr = (const float*)d_in[0];
    const float* psi = (const float*)d_in[1];
    const float* Kfr = (const float*)d_in[2];
    const float* Kfi = (const float*)d_in[3];
    const float* Kbr = (const float*)d_in[4];
    const float* Kbi = (const float*)d_in[5];
    float* out = (float*)d_out;

    const int smem = NBUF * STAGEB;   // 92160 B
    cudaFuncSetAttribute(hop_kernel, cudaFuncAttributeMaxDynamicSharedMemorySize, smem);

    dim3 block(12, 16);      // 12 rows x 16 sites = 192 threads
    dim3 grid(NV / 16);      // 2048 blocks
    hop_kernel<<<grid, block, smem>>>(psr, psi, Kfr, Kfi, Kbr, Kbi, out);
}